// round 3
// baseline (speedup 1.0000x reference)
#include <cuda_runtime.h>
#include <cstdint>

// Problem constants
#define BB      8
#define CC      512
#define NN      1024      // H*W
#define NH      8
#define CH      64        // CC / NH
#define GG      32        // groups
#define CPG     16        // channels per group
#define EPSV    1e-5f

// Scratch (device globals — no allocation allowed)
__device__ float g_hn  [(size_t)BB * CC * NN];        // 16.8 MB
__device__ float g_qkv [(size_t)BB * 3 * CC * NN];    // 50.3 MB
__device__ float g_attn[(size_t)BB * CC * NN];        // 16.8 MB
__device__ float g_proj[(size_t)BB * CC * NN];        // 16.8 MB

// ---------------------------------------------------------------------------
// GroupNorm 1: g_hn = GN(x) * scale + bias
// one block per (batch, group): 16 channels * 1024 = 16384 floats
// ---------------------------------------------------------------------------
__global__ void gn1_kernel(const float* __restrict__ x,
                           const float* __restrict__ sc,
                           const float* __restrict__ bi) {
    const int blk = blockIdx.x;
    const int b = blk / GG, g = blk % GG;
    const size_t base = ((size_t)b * CC + (size_t)g * CPG) * NN;
    const float* xp = x + base;
    const int tid = threadIdx.x;

    float s = 0.f, s2 = 0.f;
    for (int i = tid; i < CPG * NN; i += 256) {
        float v = xp[i];
        s += v; s2 += v * v;
    }
    __shared__ float r1[256], r2[256];
    r1[tid] = s; r2[tid] = s2;
    __syncthreads();
    for (int o = 128; o > 0; o >>= 1) {
        if (tid < o) { r1[tid] += r1[tid + o]; r2[tid] += r2[tid + o]; }
        __syncthreads();
    }
    __shared__ float mu_s, rstd_s;
    if (tid == 0) {
        float inv = 1.0f / (CPG * NN);
        float mu = r1[0] * inv;
        float var = r2[0] * inv - mu * mu;
        mu_s = mu; rstd_s = rsqrtf(var + EPSV);
    }
    __syncthreads();
    const float mu = mu_s, rstd = rstd_s;
    for (int i = tid; i < CPG * NN; i += 256) {
        int c = g * CPG + (i >> 10);
        g_hn[base + i] = (xp[i] - mu) * rstd * sc[c] + bi[c];
    }
}

// ---------------------------------------------------------------------------
// Tiled SGEMM: Y[b][m][n] = sum_k W[m][k] * X[b][k][n] + bias[m]
// BM=BN=128, BK=16, 256 threads, 8x8 microtile
// ---------------------------------------------------------------------------
__device__ __forceinline__ void gemm_body(const float* __restrict__ W,
                                          const float* __restrict__ bias,
                                          const float* __restrict__ X,
                                          float* __restrict__ Y,
                                          int M, int K) {
    constexpr int BM = 128, BN = 128, BK = 16;
    __shared__ float As[BK][BM];
    __shared__ float Bs[BK][BN];

    const int n0 = blockIdx.x * BN;
    const int m0 = blockIdx.y * BM;
    const int b  = blockIdx.z;
    const float* Xb = X + (size_t)b * K * NN + n0;
    float*       Yb = Y + (size_t)b * M * NN + n0;

    const int tid = threadIdx.x;
    const int tr = tid >> 4, tc = tid & 15;

    // load indices
    const int arow = tid >> 1;
    const int acol = (tid & 1) * 8;
    const int brow = tid >> 4;
    const int bcol = (tid & 15) * 8;

    float acc[8][8];
    #pragma unroll
    for (int i = 0; i < 8; i++)
        #pragma unroll
        for (int j = 0; j < 8; j++) acc[i][j] = 0.f;

    for (int k0 = 0; k0 < K; k0 += BK) {
        // W tile -> As (transposed)
        const float* wp = W + (size_t)(m0 + arow) * K + k0 + acol;
        #pragma unroll
        for (int i = 0; i < 8; i++) As[acol + i][arow] = wp[i];
        // X tile -> Bs (vectorized, coalesced)
        const float* xp = Xb + (size_t)(k0 + brow) * NN + bcol;
        float4 v0 = *(const float4*)(xp);
        float4 v1 = *(const float4*)(xp + 4);
        *(float4*)&Bs[brow][bcol]     = v0;
        *(float4*)&Bs[brow][bcol + 4] = v1;
        __syncthreads();

        #pragma unroll
        for (int k = 0; k < BK; k++) {
            float a[8], bb[8];
            #pragma unroll
            for (int i = 0; i < 8; i++) a[i]  = As[k][tr * 8 + i];
            #pragma unroll
            for (int j = 0; j < 8; j++) bb[j] = Bs[k][tc * 8 + j];
            #pragma unroll
            for (int i = 0; i < 8; i++)
                #pragma unroll
                for (int j = 0; j < 8; j++) acc[i][j] += a[i] * bb[j];
        }
        __syncthreads();
    }

    #pragma unroll
    for (int i = 0; i < 8; i++) {
        const int m = m0 + tr * 8 + i;
        const float bv = bias[m];
        #pragma unroll
        for (int j = 0; j < 8; j++)
            Yb[(size_t)m * NN + tc * 8 + j] = acc[i][j] + bv;
    }
}

__global__ void gemm_qkv_kernel(const float* __restrict__ W,
                                const float* __restrict__ bias) {
    gemm_body(W, bias, g_hn, g_qkv, 3 * CC, CC);
}

__global__ void gemm_proj_kernel(const float* __restrict__ W,
                                 const float* __restrict__ bias) {
    gemm_body(W, bias, g_attn, g_proj, CC, CC);
}

// ---------------------------------------------------------------------------
// Flash attention: per (b*head, 64-query tile). ch=64, N=1024, scale^2=0.125
// qkv layout per batch: 1536 channels, head h: q=[192h,192h+64), k=+64, v=+128
// dynamic smem: Qs,Ks,Vs,Ss = 4 * 64*65 floats = 66560 B
// ---------------------------------------------------------------------------
__global__ void attn_kernel() {
    extern __shared__ float smf[];
    float (*Qs)[65] = (float(*)[65])(smf);
    float (*Ks)[65] = (float(*)[65])(smf + 64 * 65);
    float (*Vs)[65] = (float(*)[65])(smf + 2 * 64 * 65);
    float (*Ss)[65] = (float(*)[65])(smf + 3 * 64 * 65);
    __shared__ float m_sm[64], l_sm[64], al_sm[64];

    const int bh = blockIdx.y;
    const int b = bh >> 3, h = bh & 7;
    const int q0 = blockIdx.x * 64;
    const float* qb = g_qkv + ((size_t)b * 1536 + (size_t)h * 192) * NN;
    const float* kb = qb + (size_t)64 * NN;
    const float* vb = kb + (size_t)64 * NN;

    const int tid = threadIdx.x;        // 256
    const int ti = tid >> 4, tj = tid & 15;

    // load Q tile (pre-scaled by scale^2 = 1/sqrt(64))
    for (int i = tid; i < 64 * 64; i += 256) {
        int c = i >> 6, t = i & 63;
        Qs[c][t] = qb[(size_t)c * NN + q0 + t] * 0.125f;
    }
    if (tid < 64) { m_sm[tid] = -1e30f; l_sm[tid] = 0.f; }

    float O[4][4];
    #pragma unroll
    for (int a = 0; a < 4; a++)
        #pragma unroll
        for (int x2 = 0; x2 < 4; x2++) O[a][x2] = 0.f;

    __syncthreads();

    for (int s0 = 0; s0 < NN; s0 += 64) {
        // load K,V tiles
        for (int i = tid; i < 64 * 64; i += 256) {
            int c = i >> 6, s = i & 63;
            Ks[c][s] = kb[(size_t)c * NN + s0 + s];
            Vs[c][s] = vb[(size_t)c * NN + s0 + s];
        }
        __syncthreads();

        // S = Q^T K (scale already folded into Q)
        float acc[4][4];
        #pragma unroll
        for (int a = 0; a < 4; a++)
            #pragma unroll
            for (int x2 = 0; x2 < 4; x2++) acc[a][x2] = 0.f;

        #pragma unroll 8
        for (int c = 0; c < 64; c++) {
            float qv[4], kv[4];
            #pragma unroll
            for (int a = 0; a < 4; a++)  qv[a] = Qs[c][ti * 4 + a];
            #pragma unroll
            for (int x2 = 0; x2 < 4; x2++) kv[x2] = Ks[c][tj * 4 + x2];
            #pragma unroll
            for (int a = 0; a < 4; a++)
                #pragma unroll
                for (int x2 = 0; x2 < 4; x2++) acc[a][x2] += qv[a] * kv[x2];
        }
        #pragma unroll
        for (int a = 0; a < 4; a++)
            #pragma unroll
            for (int x2 = 0; x2 < 4; x2++) Ss[ti * 4 + a][tj * 4 + x2] = acc[a][x2];
        __syncthreads();

        // online softmax row stats + in-place exp (64 threads, one per row)
        if (tid < 64) {
            float mold = m_sm[tid];
            float rmax = mold;
            #pragma unroll 8
            for (int s = 0; s < 64; s++) rmax = fmaxf(rmax, Ss[tid][s]);
            float al = __expf(mold - rmax);
            float rs = 0.f;
            #pragma unroll 8
            for (int s = 0; s < 64; s++) {
                float e = __expf(Ss[tid][s] - rmax);
                Ss[tid][s] = e;
                rs += e;
            }
            m_sm[tid] = rmax;
            l_sm[tid] = l_sm[tid] * al + rs;
            al_sm[tid] = al;
        }
        __syncthreads();

        // O = O*alpha + P @ V^T
        float al[4];
        #pragma unroll
        for (int a = 0; a < 4; a++) al[a] = al_sm[ti * 4 + a];
        #pragma unroll
        for (int a = 0; a < 4; a++)
            #pragma unroll
            for (int x2 = 0; x2 < 4; x2++) O[a][x2] *= al[a];

        #pragma unroll 8
        for (int s = 0; s < 64; s++) {
            float p[4], vv[4];
            #pragma unroll
            for (int a = 0; a < 4; a++)   p[a]  = Ss[ti * 4 + a][s];
            #pragma unroll
            for (int x2 = 0; x2 < 4; x2++) vv[x2] = Vs[tj * 4 + x2][s];
            #pragma unroll
            for (int a = 0; a < 4; a++)
                #pragma unroll
                for (int x2 = 0; x2 < 4; x2++) O[a][x2] += p[a] * vv[x2];
        }
        __syncthreads();
    }

    float linv[4];
    #pragma unroll
    for (int a = 0; a < 4; a++) linv[a] = 1.0f / l_sm[ti * 4 + a];

    // write: g_attn[b][h*64 + c][q0 + t]
    float* ob = g_attn + ((size_t)b * CC + (size_t)h * 64) * NN + q0;
    #pragma unroll
    for (int x2 = 0; x2 < 4; x2++)
        #pragma unroll
        for (int a = 0; a < 4; a++)
            ob[(size_t)(tj * 4 + x2) * NN + ti * 4 + a] = O[a][x2] * linv[a];
}

// ---------------------------------------------------------------------------
// GroupNorm 2 + residual: out = x + GN(g_proj)*scale + bias
// ---------------------------------------------------------------------------
__global__ void gn2_res_kernel(const float* __restrict__ x,
                               const float* __restrict__ sc,
                               const float* __restrict__ bi,
                               float* __restrict__ out) {
    const int blk = blockIdx.x;
    const int b = blk / GG, g = blk % GG;
    const size_t base = ((size_t)b * CC + (size_t)g * CPG) * NN;
    const float* yp = g_proj + base;
    const int tid = threadIdx.x;

    float s = 0.f, s2 = 0.f;
    for (int i = tid; i < CPG * NN; i += 256) {
        float v = yp[i];
        s += v; s2 += v * v;
    }
    __shared__ float r1[256], r2[256];
    r1[tid] = s; r2[tid] = s2;
    __syncthreads();
    for (int o = 128; o > 0; o >>= 1) {
        if (tid < o) { r1[tid] += r1[tid + o]; r2[tid] += r2[tid + o]; }
        __syncthreads();
    }
    __shared__ float mu_s, rstd_s;
    if (tid == 0) {
        float inv = 1.0f / (CPG * NN);
        float mu = r1[0] * inv;
        float var = r2[0] * inv - mu * mu;
        mu_s = mu; rstd_s = rsqrtf(var + EPSV);
    }
    __syncthreads();
    const float mu = mu_s, rstd = rstd_s;
    for (int i = tid; i < CPG * NN; i += 256) {
        int c = g * CPG + (i >> 10);
        out[base + i] = x[base + i] + (yp[i] - mu) * rstd * sc[c] + bi[c];
    }
}

// ---------------------------------------------------------------------------
extern "C" void kernel_launch(void* const* d_in, const int* in_sizes, int n_in,
                              void* d_out, int out_size) {
    const float* x        = (const float*)d_in[0];
    const float* gn1_s    = (const float*)d_in[1];
    const float* gn1_b    = (const float*)d_in[2];
    const float* w_qkv    = (const float*)d_in[3];
    const float* b_qkv    = (const float*)d_in[4];
    const float* w_proj   = (const float*)d_in[5];
    const float* b_proj   = (const float*)d_in[6];
    const float* gn2_s    = (const float*)d_in[7];
    const float* gn2_b    = (const float*)d_in[8];
    float* out = (float*)d_out;

    static const int ATTN_SMEM = 4 * 64 * 65 * (int)sizeof(float);  // 66560 B
    cudaFuncSetAttribute(attn_kernel,
                         cudaFuncAttributeMaxDynamicSharedMemorySize, ATTN_SMEM);

    // 1) GroupNorm1
    gn1_kernel<<<BB * GG, 256>>>(x, gn1_s, gn1_b);
    // 2) QKV GEMM: M=1536, N=1024, K=512, batched over 8
    gemm_qkv_kernel<<<dim3(NN / 128, (3 * CC) / 128, BB), 256>>>(w_qkv, b_qkv);
    // 3) Flash attention: 16 query tiles x 64 (batch*head)
    attn_kernel<<<dim3(NN / 64, BB * NH), 256, ATTN_SMEM>>>();
    // 4) Proj GEMM: M=512
    gemm_proj_kernel<<<dim3(NN / 128, CC / 128, BB), 256>>>(w_proj, b_proj);
    // 5) GroupNorm2 + residual
    gn2_res_kernel<<<BB * GG, 256>>>(x, gn2_s, gn2_b, out);
}

// round 7
// speedup vs baseline: 1.6031x; 1.6031x over previous
#include <cuda_runtime.h>
#include <cstdint>

// Problem constants
#define BB      8
#define CC      512
#define NN      1024      // H*W
#define NH      8
#define GG      32        // groups
#define CPG     16        // channels per group
#define EPSV    1e-5f

// Scratch (device globals — no allocation allowed)
__device__ float g_hn  [(size_t)BB * CC * NN];          // 16.8 MB  GN1 output
__device__ float g_qkv [(size_t)BB * 3 * CC * NN];      // 50.3 MB
__device__ float g_S   [(size_t)BB * NH * NN * NN];     // 268 MB   S[bh][s][t] (raw logits)
__device__ float g_mx  [(size_t)BB * NH * NN];          // per-(bh,t) running max
__device__ float g_li  [(size_t)BB * NH * NN];          // per-(bh,t) 1/sum
__device__ float g_attn[(size_t)BB * CC * NN];          // 16.8 MB
__device__ float g_proj[(size_t)BB * CC * NN];          // 16.8 MB

// ===========================================================================
// tf32 helpers
// ===========================================================================
__device__ __forceinline__ float totf(float x) {
    uint32_t r;
    asm("cvt.rna.tf32.f32 %0, %1;" : "=r"(r) : "f"(x));
    return __uint_as_float(r);
}

__device__ __forceinline__ void mma_tf32(float* c, const uint32_t* a, const uint32_t* b) {
    asm volatile(
        "mma.sync.aligned.m16n8k8.row.col.f32.tf32.tf32.f32 "
        "{%0,%1,%2,%3}, {%4,%5,%6,%7}, {%8,%9}, {%0,%1,%2,%3};"
        : "+f"(c[0]), "+f"(c[1]), "+f"(c[2]), "+f"(c[3])
        : "r"(a[0]), "r"(a[1]), "r"(a[2]), "r"(a[3]), "r"(b[0]), "r"(b[1]));
}

#define SPAD 20   // smem row pitch (floats) for a 16-float K-chunk row

struct F2 { float4 a, b; };

// ---------------------------------------------------------------------------
// Loaders. smem tile layout: [row][SPAD] with 16 valid k-floats per row.
// ---------------------------------------------------------------------------
// Direct: src[row][k], k contiguous (ld = row stride). rows = 128 or 64.
template<int ROWS>
__device__ __forceinline__ void ldg_direct(F2& f, const float* __restrict__ src,
                                           int ld, int k0, float scale) {
    const int tid = threadIdx.x;
    {
        int i = tid;                       // pass 0  (ROWS*4 quads total)
        int row = i >> 2, kq = i & 3;
        float4 v = *(const float4*)(src + (size_t)row * ld + k0 + kq * 4);
        f.a.x = totf(v.x * scale); f.a.y = totf(v.y * scale);
        f.a.z = totf(v.z * scale); f.a.w = totf(v.w * scale);
    }
    if (ROWS == 128) {
        int i = tid + 256;                 // pass 1
        int row = i >> 2, kq = i & 3;
        float4 v = *(const float4*)(src + (size_t)row * ld + k0 + kq * 4);
        f.b.x = totf(v.x * scale); f.b.y = totf(v.y * scale);
        f.b.z = totf(v.z * scale); f.b.w = totf(v.w * scale);
    }
}

template<int ROWS>
__device__ __forceinline__ void sts_direct(float* __restrict__ dst, const F2& f) {
    const int tid = threadIdx.x;
    {
        int row = tid >> 2, kq = tid & 3;
        *(float4*)(dst + row * SPAD + kq * 4) = f.a;
    }
    if (ROWS == 128) {
        int i = tid + 256;
        int row = i >> 2, kq = i & 3;
        *(float4*)(dst + row * SPAD + kq * 4) = f.b;
    }
}

// Transpose: src[k][r], r contiguous (ld = k stride). 128 rows fixed.
// Optional fused softmax: v = exp(v - mx[r]) * li[r]  (for P in AV).
template<bool SM>
__device__ __forceinline__ void ldg_trans(F2& f, const float* __restrict__ src,
                                          int ld, int k0, float scale,
                                          const float* __restrict__ mx,
                                          const float* __restrict__ li) {
    const int wid = threadIdx.x >> 5, lane = threadIdx.x & 31;
    #pragma unroll
    for (int p = 0; p < 2; p++) {
        int task = wid * 2 + p;            // 0..15: 4 k-quads x 4 row-blocks
        int q = task & 3, rj = task >> 2;
        int r = rj * 32 + lane;
        const float* pp = src + (size_t)(k0 + q * 4) * ld + r;
        float4 v;
        v.x = pp[0]; v.y = pp[(size_t)ld]; v.z = pp[(size_t)2 * ld]; v.w = pp[(size_t)3 * ld];
        if (SM) {
            float M = mx[r], L = li[r];
            v.x = __expf(v.x - M) * L; v.y = __expf(v.y - M) * L;
            v.z = __expf(v.z - M) * L; v.w = __expf(v.w - M) * L;
        }
        v.x = totf(v.x * scale); v.y = totf(v.y * scale);
        v.z = totf(v.z * scale); v.w = totf(v.w * scale);
        if (p == 0) f.a = v; else f.b = v;
    }
}

__device__ __forceinline__ void sts_trans(float* __restrict__ dst, const F2& f) {
    const int wid = threadIdx.x >> 5, lane = threadIdx.x & 31;
    #pragma unroll
    for (int p = 0; p < 2; p++) {
        int task = wid * 2 + p;
        int q = task & 3, rj = task >> 2;
        int r = rj * 32 + lane;
        *(float4*)(dst + r * SPAD + q * 4) = (p == 0) ? f.a : f.b;
    }
}

// ===========================================================================
// Unified tf32 mma.sync GEMM core.
//   D[c (BM = MT*32)][r (128)] = sum_k A[c][k] * B[k][r]
//   A: direct (TA=false, src[c][k]) or transpose (TA=true, src[k][c])
//   B: always transpose-loaded (src[k][r], r contiguous)
//   Out[c * NN + r] (+ bias[c]); callers pre-offset all pointers to the tile.
// 8 warps = 2 (M) x 4 (N); warp tile = (MT*16) x 32; mma m16n8k8.
// ===========================================================================
template<int MT, bool TA, bool SM>
__device__ __forceinline__ void gemm_core(
    const float* __restrict__ Asrc, int ldA, float scaleA,
    const float* __restrict__ Bsrc, int ldB,
    const float* __restrict__ mx, const float* __restrict__ li,
    float* __restrict__ Out, const float* __restrict__ bias, int K)
{
    constexpr int ROWS_A = MT * 32;
    __shared__ float As[2][128 * SPAD];
    __shared__ float Bs[2][128 * SPAD];

    const int tid = threadIdx.x;
    const int wid = tid >> 5, lane = tid & 31;
    const int wm = wid & 1, wn = wid >> 1;
    const int grp = lane >> 2, tig = lane & 3;

    float acc[MT][4][4];
    #pragma unroll
    for (int i = 0; i < MT; i++)
        #pragma unroll
        for (int j = 0; j < 4; j++)
            #pragma unroll
            for (int e = 0; e < 4; e++) acc[i][j][e] = 0.f;

    const int nK = K >> 4;
    F2 fa, fb;

    // prologue: tile 0
    if (TA) ldg_trans<false>(fa, Asrc, ldA, 0, scaleA, nullptr, nullptr);
    else    ldg_direct<ROWS_A>(fa, Asrc, ldA, 0, scaleA);
    ldg_trans<SM>(fb, Bsrc, ldB, 0, 1.f, mx, li);
    if (TA) sts_trans(As[0], fa);
    else    sts_direct<ROWS_A>(As[0], fa);
    sts_trans(Bs[0], fb);
    __syncthreads();

    for (int it = 0; it < nK; it++) {
        const int cur = it & 1;
        if (it + 1 < nK) {
            if (TA) ldg_trans<false>(fa, Asrc, ldA, (it + 1) * 16, scaleA, nullptr, nullptr);
            else    ldg_direct<ROWS_A>(fa, Asrc, ldA, (it + 1) * 16, scaleA);
            ldg_trans<SM>(fb, Bsrc, ldB, (it + 1) * 16, 1.f, mx, li);
        }

        const float* Ab = As[cur];
        const float* Bb = Bs[cur];
        #pragma unroll
        for (int kk = 0; kk < 2; kk++) {
            uint32_t a[MT][4];
            #pragma unroll
            for (int i = 0; i < MT; i++) {
                int c = wm * MT * 16 + i * 16 + grp;
                int k = kk * 8 + tig;
                a[i][0] = __float_as_uint(Ab[c * SPAD + k]);
                a[i][1] = __float_as_uint(Ab[(c + 8) * SPAD + k]);
                a[i][2] = __float_as_uint(Ab[c * SPAD + k + 4]);
                a[i][3] = __float_as_uint(Ab[(c + 8) * SPAD + k + 4]);
            }
            uint32_t b[4][2];
            #pragma unroll
            for (int j = 0; j < 4; j++) {
                int r = wn * 32 + j * 8 + grp;
                int k = kk * 8 + tig;
                b[j][0] = __float_as_uint(Bb[r * SPAD + k]);
                b[j][1] = __float_as_uint(Bb[r * SPAD + k + 4]);
            }
            #pragma unroll
            for (int i = 0; i < MT; i++)
                #pragma unroll
                for (int j = 0; j < 4; j++)
                    mma_tf32(acc[i][j], a[i], b[j]);
        }

        if (it + 1 < nK) {
            if (TA) sts_trans(As[cur ^ 1], fa);
            else    sts_direct<ROWS_A>(As[cur ^ 1], fa);
            sts_trans(Bs[cur ^ 1], fb);
        }
        __syncthreads();
    }

    // epilogue: coalesced-ish float2 stores (8 consecutive floats per group row)
    #pragma unroll
    for (int i = 0; i < MT; i++) {
        int c = wm * MT * 16 + i * 16 + grp;
        float bv0 = bias ? bias[c] : 0.f;
        float bv1 = bias ? bias[c + 8] : 0.f;
        #pragma unroll
        for (int j = 0; j < 4; j++) {
            int r = wn * 32 + j * 8 + tig * 2;
            float2 v0 = { acc[i][j][0] + bv0, acc[i][j][1] + bv0 };
            float2 v1 = { acc[i][j][2] + bv1, acc[i][j][3] + bv1 };
            *(float2*)&Out[(size_t)c * NN + r] = v0;
            *(float2*)&Out[(size_t)(c + 8) * NN + r] = v1;
        }
    }
}

// ===========================================================================
// GEMM wrapper kernels
// ===========================================================================
// qkv: D[m][n] = W[m][k] * hn[k][n].  A direct, B trans.
__global__ void __launch_bounds__(256) k_qkv(const float* __restrict__ W,
                                             const float* __restrict__ bias) {
    int n0 = blockIdx.x * 128, m0 = blockIdx.y * 128, b = blockIdx.z;
    gemm_core<4, false, false>(
        W + (size_t)m0 * CC, CC, 1.f,
        g_hn + (size_t)b * CC * NN + n0, NN, nullptr, nullptr,
        g_qkv + (size_t)b * 3 * CC * NN + (size_t)m0 * NN + n0, bias + m0, CC);
}

// S: S[s][t] = sum_c (0.125*K[c][s]) * Q[c][t].  A trans (K), B trans (Q).
__global__ void __launch_bounds__(256) k_sgemm() {
    int t0 = blockIdx.x * 128, s0 = blockIdx.y * 128, bh = blockIdx.z;
    int b = bh >> 3, h = bh & 7;
    const float* qb = g_qkv + ((size_t)b * 1536 + (size_t)h * 192) * NN;
    gemm_core<4, true, false>(
        qb + (size_t)64 * NN + s0, NN, 0.125f,    // A = K-matrix [c][s]
        qb + t0, NN, nullptr, nullptr,            // B = Q [c][t]
        g_S + (size_t)bh * NN * NN + (size_t)s0 * NN + t0, nullptr, 64);
}

// AV: A[c][t] = sum_s V[c][s] * P[s][t], P = exp(S - mx)*li fused in B loader.
__global__ void __launch_bounds__(256) k_av() {
    int t0 = blockIdx.x * 128, bh = blockIdx.z;
    int b = bh >> 3, h = bh & 7;
    gemm_core<2, false, true>(
        g_qkv + ((size_t)b * 1536 + (size_t)h * 192 + 128) * NN, NN, 1.f,  // V direct
        g_S + (size_t)bh * NN * NN + t0, NN,                                // S[s][t]
        g_mx + (size_t)bh * NN + t0, g_li + (size_t)bh * NN + t0,
        g_attn + ((size_t)b * CC + (size_t)h * 64) * NN + t0, nullptr, NN);
}

// proj: D[m][n] = Wp[m][k] * attn[k][n]
__global__ void __launch_bounds__(256) k_proj(const float* __restrict__ W,
                                              const float* __restrict__ bias) {
    int n0 = blockIdx.x * 128, m0 = blockIdx.y * 128, b = blockIdx.z;
    gemm_core<4, false, false>(
        W + (size_t)m0 * CC, CC, 1.f,
        g_attn + (size_t)b * CC * NN + n0, NN, nullptr, nullptr,
        g_proj + (size_t)b * CC * NN + (size_t)m0 * NN + n0, bias + m0, CC);
}

// ===========================================================================
// Softmax stats: per (bh, t) compute M = max_s S, li = 1/sum_s exp(S-M).
// One read of g_S; normalization is fused into the AV loader.
// ===========================================================================
__global__ void stats_kernel() {
    __shared__ float sm[4][64], sl[4][64];
    const int bh = blockIdx.y;
    const int tl = threadIdx.x & 63;
    const int grpi = threadIdx.x >> 6;
    const float* base = g_S + (size_t)bh * NN * NN + blockIdx.x * 64 + tl;

    float m = -1e30f, l = 0.f;
    for (int s = grpi; s < NN; s += 4) {
        float v = base[(size_t)s * NN];
        if (v <= m) l += __expf(v - m);
        else { l = l * __expf(m - v) + 1.f; m = v; }
    }
    sm[grpi][tl] = m; sl[grpi][tl] = l;
    __syncthreads();
    if (threadIdx.x < 64) {
        float M = sm[0][tl];
        #pragma unroll
        for (int i = 1; i < 4; i++) M = fmaxf(M, sm[i][tl]);
        float L = 0.f;
        #pragma unroll
        for (int i = 0; i < 4; i++) L += sl[i][tl] * __expf(sm[i][tl] - M);
        int t = blockIdx.x * 64 + tl;
        g_mx[(size_t)bh * NN + t] = M;
        g_li[(size_t)bh * NN + t] = 1.f / L;
    }
}

// ===========================================================================
// GroupNorm kernels
// ===========================================================================
__global__ void gn1_kernel(const float* __restrict__ x,
                           const float* __restrict__ sc,
                           const float* __restrict__ bi) {
    const int blk = blockIdx.x;
    const int b = blk / GG, g = blk % GG;
    const size_t base = ((size_t)b * CC + (size_t)g * CPG) * NN;
    const float* xp = x + base;
    const int tid = threadIdx.x;

    float s = 0.f, s2 = 0.f;
    for (int i = tid; i < CPG * NN; i += 256) {
        float v = xp[i];
        s += v; s2 += v * v;
    }
    __shared__ float r1[256], r2[256];
    r1[tid] = s; r2[tid] = s2;
    __syncthreads();
    for (int o = 128; o > 0; o >>= 1) {
        if (tid < o) { r1[tid] += r1[tid + o]; r2[tid] += r2[tid + o]; }
        __syncthreads();
    }
    __shared__ float mu_s, rstd_s;
    if (tid == 0) {
        float inv = 1.0f / (CPG * NN);
        float mu = r1[0] * inv;
        float var = r2[0] * inv - mu * mu;
        mu_s = mu; rstd_s = rsqrtf(var + EPSV);
    }
    __syncthreads();
    const float mu = mu_s, rstd = rstd_s;
    for (int i = tid; i < CPG * NN; i += 256) {
        int c = g * CPG + (i >> 10);
        g_hn[base + i] = (xp[i] - mu) * rstd * sc[c] + bi[c];
    }
}

__global__ void gn2_res_kernel(const float* __restrict__ x,
                               const float* __restrict__ sc,
                               const float* __restrict__ bi,
                               float* __restrict__ out) {
    const int blk = blockIdx.x;
    const int b = blk / GG, g = blk % GG;
    const size_t base = ((size_t)b * CC + (size_t)g * CPG) * NN;
    const float* yp = g_proj + base;
    const int tid = threadIdx.x;

    float s = 0.f, s2 = 0.f;
    for (int i = tid; i < CPG * NN; i += 256) {
        float v = yp[i];
        s += v; s2 += v * v;
    }
    __shared__ float r1[256], r2[256];
    r1[tid] = s; r2[tid] = s2;
    __syncthreads();
    for (int o = 128; o > 0; o >>= 1) {
        if (tid < o) { r1[tid] += r1[tid + o]; r2[tid] += r2[tid + o]; }
        __syncthreads();
    }
    __shared__ float mu_s, rstd_s;
    if (tid == 0) {
        float inv = 1.0f / (CPG * NN);
        float mu = r1[0] * inv;
        float var = r2[0] * inv - mu * mu;
        mu_s = mu; rstd_s = rsqrtf(var + EPSV);
    }
    __syncthreads();
    const float mu = mu_s, rstd = rstd_s;
    for (int i = tid; i < CPG * NN; i += 256) {
        int c = g * CPG + (i >> 10);
        out[base + i] = x[base + i] + (yp[i] - mu) * rstd * sc[c] + bi[c];
    }
}

// ---------------------------------------------------------------------------
extern "C" void kernel_launch(void* const* d_in, const int* in_sizes, int n_in,
                              void* d_out, int out_size) {
    const float* x        = (const float*)d_in[0];
    const float* gn1_s    = (const float*)d_in[1];
    const float* gn1_b    = (const float*)d_in[2];
    const float* w_qkv    = (const float*)d_in[3];
    const float* b_qkv    = (const float*)d_in[4];
    const float* w_proj   = (const float*)d_in[5];
    const float* b_proj   = (const float*)d_in[6];
    const float* gn2_s    = (const float*)d_in[7];
    const float* gn2_b    = (const float*)d_in[8];
    float* out = (float*)d_out;

    // 1) GroupNorm1
    gn1_kernel<<<BB * GG, 256>>>(x, gn1_s, gn1_b);
    // 2) QKV: [8] x (1536 x 1024 x 512)
    k_qkv<<<dim3(8, 12, BB), 256>>>(w_qkv, b_qkv);
    // 3) S = 0.125 * K^T Q per (b,h): [64] x (1024 x 1024 x 64), stored [s][t]
    k_sgemm<<<dim3(8, 8, BB * NH), 256>>>();
    // 4) softmax stats (max + 1/sum per column t)
    stats_kernel<<<dim3(16, BB * NH), 256>>>();
    // 5) A = V P (P materialized on the fly): [8] x (64 x 1024 x 1024)
    k_av<<<dim3(8, 1, BB * NH), 256>>>();
    // 6) proj: [8] x (512 x 1024 x 512)
    k_proj<<<dim3(8, 4, BB), 256>>>(w_proj, b_proj);
    // 7) GroupNorm2 + residual
    gn2_res_kernel<<<BB * GG, 256>>>(x, gn2_s, gn2_b, out);
}

// round 9
// speedup vs baseline: 3.3017x; 2.0596x over previous
#include <cuda_runtime.h>
#include <cstdint>

// Problem constants
#define BB      8
#define CC      512
#define NN      1024      // H*W
#define NH      8
#define GG      32        // groups
#define CPG     16        // channels per group
#define EPSV    1e-5f

// Scratch (device globals — no allocation allowed)
__device__ float g_hn  [(size_t)BB * CC * NN];          // 16.8 MB  GN1 output
__device__ float g_qkv [(size_t)BB * 3 * CC * NN];      // 50.3 MB
__device__ float g_attn[(size_t)BB * CC * NN];          // 16.8 MB
__device__ float g_proj[(size_t)BB * CC * NN];          // 16.8 MB

// ===========================================================================
// tf32 helpers
// ===========================================================================
__device__ __forceinline__ float totf(float x) {
    uint32_t r;
    asm("cvt.rna.tf32.f32 %0, %1;" : "=r"(r) : "f"(x));
    return __uint_as_float(r);
}

__device__ __forceinline__ void mma_tf32(float* c, const uint32_t* a, const uint32_t* b) {
    asm volatile(
        "mma.sync.aligned.m16n8k8.row.col.f32.tf32.tf32.f32 "
        "{%0,%1,%2,%3}, {%4,%5,%6,%7}, {%8,%9}, {%0,%1,%2,%3};"
        : "+f"(c[0]), "+f"(c[1]), "+f"(c[2]), "+f"(c[3])
        : "r"(a[0]), "r"(a[1]), "r"(a[2]), "r"(a[3]), "r"(b[0]), "r"(b[1]));
}

#define SPAD 20   // smem row pitch (floats) for a 16-float K-chunk row

struct F2 { float4 a, b; };

// ---------------------------------------------------------------------------
// Loaders for the generic GEMM (qkv / proj). smem tile: [row][SPAD], 16 k/row.
// ---------------------------------------------------------------------------
template<int ROWS>
__device__ __forceinline__ void ldg_direct(F2& f, const float* __restrict__ src,
                                           int ld, int k0, float scale) {
    const int tid = threadIdx.x;
    {
        int i = tid;
        int row = i >> 2, kq = i & 3;
        float4 v = *(const float4*)(src + (size_t)row * ld + k0 + kq * 4);
        f.a.x = totf(v.x * scale); f.a.y = totf(v.y * scale);
        f.a.z = totf(v.z * scale); f.a.w = totf(v.w * scale);
    }
    if (ROWS == 128) {
        int i = tid + 256;
        int row = i >> 2, kq = i & 3;
        float4 v = *(const float4*)(src + (size_t)row * ld + k0 + kq * 4);
        f.b.x = totf(v.x * scale); f.b.y = totf(v.y * scale);
        f.b.z = totf(v.z * scale); f.b.w = totf(v.w * scale);
    }
}

template<int ROWS>
__device__ __forceinline__ void sts_direct(float* __restrict__ dst, const F2& f) {
    const int tid = threadIdx.x;
    {
        int row = tid >> 2, kq = tid & 3;
        *(float4*)(dst + row * SPAD + kq * 4) = f.a;
    }
    if (ROWS == 128) {
        int i = tid + 256;
        int row = i >> 2, kq = i & 3;
        *(float4*)(dst + row * SPAD + kq * 4) = f.b;
    }
}

__device__ __forceinline__ void ldg_trans(F2& f, const float* __restrict__ src,
                                          int ld, int k0, float scale) {
    const int wid = threadIdx.x >> 5, lane = threadIdx.x & 31;
    #pragma unroll
    for (int p = 0; p < 2; p++) {
        int task = wid * 2 + p;
        int q = task & 3, rj = task >> 2;
        int r = rj * 32 + lane;
        const float* pp = src + (size_t)(k0 + q * 4) * ld + r;
        float4 v;
        v.x = pp[0]; v.y = pp[(size_t)ld]; v.z = pp[(size_t)2 * ld]; v.w = pp[(size_t)3 * ld];
        v.x = totf(v.x * scale); v.y = totf(v.y * scale);
        v.z = totf(v.z * scale); v.w = totf(v.w * scale);
        if (p == 0) f.a = v; else f.b = v;
    }
}

__device__ __forceinline__ void sts_trans(float* __restrict__ dst, const F2& f) {
    const int wid = threadIdx.x >> 5, lane = threadIdx.x & 31;
    #pragma unroll
    for (int p = 0; p < 2; p++) {
        int task = wid * 2 + p;
        int q = task & 3, rj = task >> 2;
        int r = rj * 32 + lane;
        *(float4*)(dst + r * SPAD + q * 4) = (p == 0) ? f.a : f.b;
    }
}

// ===========================================================================
// Generic tf32 mma.sync GEMM core (for qkv / proj).
//   D[c (128)][r (128)] = sum_k A[c][k] * B[k][r], A direct, B transpose.
// 8 warps = 2 (M) x 4 (N); warp tile 64x32; mma m16n8k8.
// ===========================================================================
__device__ __forceinline__ void gemm_core(
    const float* __restrict__ Asrc, int ldA,
    const float* __restrict__ Bsrc, int ldB,
    float* __restrict__ Out, const float* __restrict__ bias, int K)
{
    __shared__ float As[2][128 * SPAD];
    __shared__ float Bs[2][128 * SPAD];

    const int tid = threadIdx.x;
    const int wid = tid >> 5, lane = tid & 31;
    const int wm = wid & 1, wn = wid >> 1;
    const int grp = lane >> 2, tig = lane & 3;

    float acc[4][4][4];
    #pragma unroll
    for (int i = 0; i < 4; i++)
        #pragma unroll
        for (int j = 0; j < 4; j++)
            #pragma unroll
            for (int e = 0; e < 4; e++) acc[i][j][e] = 0.f;

    const int nK = K >> 4;
    F2 fa, fb;

    ldg_direct<128>(fa, Asrc, ldA, 0, 1.f);
    ldg_trans(fb, Bsrc, ldB, 0, 1.f);
    sts_direct<128>(As[0], fa);
    sts_trans(Bs[0], fb);
    __syncthreads();

    for (int it = 0; it < nK; it++) {
        const int cur = it & 1;
        if (it + 1 < nK) {
            ldg_direct<128>(fa, Asrc, ldA, (it + 1) * 16, 1.f);
            ldg_trans(fb, Bsrc, ldB, (it + 1) * 16, 1.f);
        }

        const float* Ab = As[cur];
        const float* Bb = Bs[cur];
        #pragma unroll
        for (int kk = 0; kk < 2; kk++) {
            uint32_t a[4][4];
            #pragma unroll
            for (int i = 0; i < 4; i++) {
                int c = wm * 64 + i * 16 + grp;
                int k = kk * 8 + tig;
                a[i][0] = __float_as_uint(Ab[c * SPAD + k]);
                a[i][1] = __float_as_uint(Ab[(c + 8) * SPAD + k]);
                a[i][2] = __float_as_uint(Ab[c * SPAD + k + 4]);
                a[i][3] = __float_as_uint(Ab[(c + 8) * SPAD + k + 4]);
            }
            uint32_t b[4][2];
            #pragma unroll
            for (int j = 0; j < 4; j++) {
                int r = wn * 32 + j * 8 + grp;
                int k = kk * 8 + tig;
                b[j][0] = __float_as_uint(Bb[r * SPAD + k]);
                b[j][1] = __float_as_uint(Bb[r * SPAD + k + 4]);
            }
            #pragma unroll
            for (int i = 0; i < 4; i++)
                #pragma unroll
                for (int j = 0; j < 4; j++)
                    mma_tf32(acc[i][j], a[i], b[j]);
        }

        if (it + 1 < nK) {
            sts_direct<128>(As[cur ^ 1], fa);
            sts_trans(Bs[cur ^ 1], fb);
        }
        __syncthreads();
    }

    #pragma unroll
    for (int i = 0; i < 4; i++) {
        int c = wm * 64 + i * 16 + grp;
        float bv0 = bias ? bias[c] : 0.f;
        float bv1 = bias ? bias[c + 8] : 0.f;
        #pragma unroll
        for (int j = 0; j < 4; j++) {
            int r = wn * 32 + j * 8 + tig * 2;
            float2 v0 = { acc[i][j][0] + bv0, acc[i][j][1] + bv0 };
            float2 v1 = { acc[i][j][2] + bv1, acc[i][j][3] + bv1 };
            *(float2*)&Out[(size_t)c * NN + r] = v0;
            *(float2*)&Out[(size_t)(c + 8) * NN + r] = v1;
        }
    }
}

__global__ void __launch_bounds__(256) k_qkv(const float* __restrict__ W,
                                             const float* __restrict__ bias) {
    int n0 = blockIdx.x * 128, m0 = blockIdx.y * 128, b = blockIdx.z;
    gemm_core(W + (size_t)m0 * CC, CC,
              g_hn + (size_t)b * CC * NN + n0, NN,
              g_qkv + (size_t)b * 3 * CC * NN + (size_t)m0 * NN + n0, bias + m0, CC);
}

__global__ void __launch_bounds__(256) k_proj(const float* __restrict__ W,
                                              const float* __restrict__ bias) {
    int n0 = blockIdx.x * 128, m0 = blockIdx.y * 128, b = blockIdx.z;
    gemm_core(W + (size_t)m0 * CC, CC,
              g_attn + (size_t)b * CC * NN + n0, NN,
              g_proj + (size_t)b * CC * NN + (size_t)m0 * NN + n0, bias + m0, CC);
}

// ===========================================================================
// Flash attention (tf32 mma.sync, fully fused softmax).
// One block = one (bh, 128-query tile). 8 warps; warp w owns t-rows
// [w*16, w*16+16). Loop over 16 s-blocks of 64.
// smem (floats):  Qs [64 c][136]     (stride 136 ≡ 8 mod 32)
//                 Ks [64 c][72]      (stride 72  ≡ 8)
//                 Vs [64 c'][68]     (stride 68  ≡ 4)
//                 Ps [8 w][16 t][68] (stride 68  ≡ 4)
// All mma fragment LDS patterns conflict-free by construction.
// ===========================================================================
#define QSTR 136
#define KSTR 72
#define VSTR 68
#define PSTR 68
#define SM_Q 0
#define SM_K (64 * QSTR)              // 8704
#define SM_V (SM_K + 64 * KSTR)       // 13312
#define SM_P (SM_V + 64 * VSTR)       // 17664
#define SM_TOT (SM_P + 8 * 16 * PSTR) // 26368 floats = 105472 B

__global__ void __launch_bounds__(256, 2) k_flash() {
    extern __shared__ float sm[];
    float* Qs = sm + SM_Q;
    float* Ks = sm + SM_K;
    float* Vs = sm + SM_V;
    float* Ps = sm + SM_P;

    const int bh = blockIdx.y;
    const int b = bh >> 3, h = bh & 7;
    const int t0 = blockIdx.x * 128;
    const float* qb = g_qkv + ((size_t)b * 1536 + (size_t)h * 192) * NN;
    const float* kb = qb + (size_t)64 * NN;
    const float* vb = qb + (size_t)128 * NN;

    const int tid = threadIdx.x;
    const int w = tid >> 5, lane = tid & 31;
    const int grp = lane >> 2, tig = lane & 3;

    // Load Q tile [64 c][128 t] (coalesced along t), rna-cvt to tf32.
    #pragma unroll
    for (int p = 0; p < 8; p++) {
        int idx = p * 1024 + tid * 4;
        int c = idx >> 7, t = idx & 127;
        float4 v = *(const float4*)(qb + (size_t)c * NN + t0 + t);
        v.x = totf(v.x); v.y = totf(v.y); v.z = totf(v.z); v.w = totf(v.w);
        *(float4*)(Qs + c * QSTR + t) = v;
    }

    float m0 = -1e30f, m1 = -1e30f, l0 = 0.f, l1 = 0.f;
    float O[8][4];
    #pragma unroll
    for (int j = 0; j < 8; j++)
        #pragma unroll
        for (int e = 0; e < 4; e++) O[j][e] = 0.f;

    for (int s0 = 0; s0 < NN; s0 += 64) {
        __syncthreads();   // previous iter's consumers done (and Q ready, iter 0)
        // Load K, V tiles [64 c][64 s] (coalesced along s), rna-cvt.
        #pragma unroll
        for (int p = 0; p < 4; p++) {
            int idx = p * 1024 + tid * 4;
            int c = idx >> 6, s = idx & 63;
            float4 kv = *(const float4*)(kb + (size_t)c * NN + s0 + s);
            kv.x = totf(kv.x); kv.y = totf(kv.y); kv.z = totf(kv.z); kv.w = totf(kv.w);
            *(float4*)(Ks + c * KSTR + s) = kv;
            float4 vv = *(const float4*)(vb + (size_t)c * NN + s0 + s);
            vv.x = totf(vv.x); vv.y = totf(vv.y); vv.z = totf(vv.z); vv.w = totf(vv.w);
            *(float4*)(Vs + c * VSTR + s) = vv;
        }
        __syncthreads();

        // S = Q^T K : M=16 (warp t-rows), N=64 (s), K=64 (c)
        float acc[8][4];
        #pragma unroll
        for (int j = 0; j < 8; j++)
            #pragma unroll
            for (int e = 0; e < 4; e++) acc[j][e] = 0.f;

        #pragma unroll
        for (int kk = 0; kk < 8; kk++) {
            uint32_t a[4];
            int ab = (kk * 8 + tig) * QSTR + w * 16 + grp;
            a[0] = __float_as_uint(Qs[ab]);
            a[1] = __float_as_uint(Qs[ab + 8]);
            a[2] = __float_as_uint(Qs[ab + 4 * QSTR]);
            a[3] = __float_as_uint(Qs[ab + 4 * QSTR + 8]);
            #pragma unroll
            for (int j = 0; j < 8; j++) {
                uint32_t bf[2];
                int bb = (kk * 8 + tig) * KSTR + j * 8 + grp;
                bf[0] = __float_as_uint(Ks[bb]);
                bf[1] = __float_as_uint(Ks[bb + 4 * KSTR]);
                mma_tf32(acc[j], a, bf);
            }
        }

        // scale logits
        #pragma unroll
        for (int j = 0; j < 8; j++)
            #pragma unroll
            for (int e = 0; e < 4; e++) acc[j][e] *= 0.125f;

        // online softmax (rows t = w*16+grp and +8; cols spread over quad)
        float rx0 = -1e30f, rx1 = -1e30f;
        #pragma unroll
        for (int j = 0; j < 8; j++) {
            rx0 = fmaxf(rx0, fmaxf(acc[j][0], acc[j][1]));
            rx1 = fmaxf(rx1, fmaxf(acc[j][2], acc[j][3]));
        }
        rx0 = fmaxf(rx0, __shfl_xor_sync(0xffffffffu, rx0, 1));
        rx0 = fmaxf(rx0, __shfl_xor_sync(0xffffffffu, rx0, 2));
        rx1 = fmaxf(rx1, __shfl_xor_sync(0xffffffffu, rx1, 1));
        rx1 = fmaxf(rx1, __shfl_xor_sync(0xffffffffu, rx1, 2));

        float mn0 = fmaxf(m0, rx0), mn1 = fmaxf(m1, rx1);
        float al0 = __expf(m0 - mn0), al1 = __expf(m1 - mn1);
        m0 = mn0; m1 = mn1;

        float rs0 = 0.f, rs1 = 0.f;
        float* pw = Ps + w * 16 * PSTR;
        #pragma unroll
        for (int j = 0; j < 8; j++) {
            float p0 = __expf(acc[j][0] - mn0);
            float p1 = __expf(acc[j][1] - mn0);
            float p2 = __expf(acc[j][2] - mn1);
            float p3 = __expf(acc[j][3] - mn1);
            rs0 += p0 + p1; rs1 += p2 + p3;
            int col = j * 8 + tig * 2;
            float2 q01 = { totf(p0), totf(p1) };
            float2 q23 = { totf(p2), totf(p3) };
            *(float2*)(pw + grp * PSTR + col) = q01;
            *(float2*)(pw + (grp + 8) * PSTR + col) = q23;
        }
        rs0 += __shfl_xor_sync(0xffffffffu, rs0, 1);
        rs0 += __shfl_xor_sync(0xffffffffu, rs0, 2);
        rs1 += __shfl_xor_sync(0xffffffffu, rs1, 1);
        rs1 += __shfl_xor_sync(0xffffffffu, rs1, 2);
        l0 = l0 * al0 + rs0;
        l1 = l1 * al1 + rs1;

        #pragma unroll
        for (int j = 0; j < 8; j++) {
            O[j][0] *= al0; O[j][1] *= al0;
            O[j][2] *= al1; O[j][3] *= al1;
        }
        __syncwarp();

        // O += P V^T : M=16 (t), N=64 (c'), K=64 (s)
        #pragma unroll
        for (int kk = 0; kk < 8; kk++) {
            uint32_t a[4];
            int ab = w * 16 * PSTR + grp * PSTR + kk * 8 + tig;
            a[0] = __float_as_uint(Ps[ab]);
            a[1] = __float_as_uint(Ps[ab + 8 * PSTR]);
            a[2] = __float_as_uint(Ps[ab + 4]);
            a[3] = __float_as_uint(Ps[ab + 8 * PSTR + 4]);
            #pragma unroll
            for (int j = 0; j < 8; j++) {
                uint32_t bf[2];
                int bb = (j * 8 + grp) * VSTR + kk * 8 + tig;
                bf[0] = __float_as_uint(Vs[bb]);
                bf[1] = __float_as_uint(Vs[bb + 4]);
                mma_tf32(O[j], a, bf);
            }
        }
    }

    // epilogue: normalize and write g_attn[b][h*64 + c'][t0 + t]
    float inv0 = 1.f / l0, inv1 = 1.f / l1;
    float* ob = g_attn + ((size_t)b * CC + (size_t)h * 64) * NN + t0;
    int tr0 = w * 16 + grp, tr1 = tr0 + 8;
    #pragma unroll
    for (int j = 0; j < 8; j++) {
        int c0 = j * 8 + tig * 2;
        ob[(size_t)c0 * NN + tr0]       = O[j][0] * inv0;
        ob[(size_t)(c0 + 1) * NN + tr0] = O[j][1] * inv0;
        ob[(size_t)c0 * NN + tr1]       = O[j][2] * inv1;
        ob[(size_t)(c0 + 1) * NN + tr1] = O[j][3] * inv1;
    }
}

// ===========================================================================
// GroupNorm kernels
// ===========================================================================
__global__ void gn1_kernel(const float* __restrict__ x,
                           const float* __restrict__ sc,
                           const float* __restrict__ bi) {
    const int blk = blockIdx.x;
    const int b = blk / GG, g = blk % GG;
    const size_t base = ((size_t)b * CC + (size_t)g * CPG) * NN;
    const float* xp = x + base;
    const int tid = threadIdx.x;

    float s = 0.f, s2 = 0.f;
    for (int i = tid; i < CPG * NN; i += 256) {
        float v = xp[i];
        s += v; s2 += v * v;
    }
    __shared__ float r1[256], r2[256];
    r1[tid] = s; r2[tid] = s2;
    __syncthreads();
    for (int o = 128; o > 0; o >>= 1) {
        if (tid < o) { r1[tid] += r1[tid + o]; r2[tid] += r2[tid + o]; }
        __syncthreads();
    }
    __shared__ float mu_s, rstd_s;
    if (tid == 0) {
        float inv = 1.0f / (CPG * NN);
        float mu = r1[0] * inv;
        float var = r2[0] * inv - mu * mu;
        mu_s = mu; rstd_s = rsqrtf(var + EPSV);
    }
    __syncthreads();
    const float mu = mu_s, rstd = rstd_s;
    for (int i = tid; i < CPG * NN; i += 256) {
        int c = g * CPG + (i >> 10);
        g_hn[base + i] = (xp[i] - mu) * rstd * sc[c] + bi[c];
    }
}

__global__ void gn2_res_kernel(const float* __restrict__ x,
                               const float* __restrict__ sc,
                               const float* __restrict__ bi,
                               float* __restrict__ out) {
    const int blk = blockIdx.x;
    const int b = blk / GG, g = blk % GG;
    const size_t base = ((size_t)b * CC + (size_t)g * CPG) * NN;
    const float* yp = g_proj + base;
    const int tid = threadIdx.x;

    float s = 0.f, s2 = 0.f;
    for (int i = tid; i < CPG * NN; i += 256) {
        float v = yp[i];
        s += v; s2 += v * v;
    }
    __shared__ float r1[256], r2[256];
    r1[tid] = s; r2[tid] = s2;
    __syncthreads();
    for (int o = 128; o > 0; o >>= 1) {
        if (tid < o) { r1[tid] += r1[tid + o]; r2[tid] += r2[tid + o]; }
        __syncthreads();
    }
    __shared__ float mu_s, rstd_s;
    if (tid == 0) {
        float inv = 1.0f / (CPG * NN);
        float mu = r1[0] * inv;
        float var = r2[0] * inv - mu * mu;
        mu_s = mu; rstd_s = rsqrtf(var + EPSV);
    }
    __syncthreads();
    const float mu = mu_s, rstd = rstd_s;
    for (int i = tid; i < CPG * NN; i += 256) {
        int c = g * CPG + (i >> 10);
        out[base + i] = x[base + i] + (yp[i] - mu) * rstd * sc[c] + bi[c];
    }
}

// ---------------------------------------------------------------------------
extern "C" void kernel_launch(void* const* d_in, const int* in_sizes, int n_in,
                              void* d_out, int out_size) {
    const float* x        = (const float*)d_in[0];
    const float* gn1_s    = (const float*)d_in[1];
    const float* gn1_b    = (const float*)d_in[2];
    const float* w_qkv    = (const float*)d_in[3];
    const float* b_qkv    = (const float*)d_in[4];
    const float* w_proj   = (const float*)d_in[5];
    const float* b_proj   = (const float*)d_in[6];
    const float* gn2_s    = (const float*)d_in[7];
    const float* gn2_b    = (const float*)d_in[8];
    float* out = (float*)d_out;

    const int FSMEM = SM_TOT * (int)sizeof(float);   // 105472 B
    cudaFuncSetAttribute(k_flash, cudaFuncAttributeMaxDynamicSharedMemorySize, FSMEM);

    // 1) GroupNorm1
    gn1_kernel<<<BB * GG, 256>>>(x, gn1_s, gn1_b);
    // 2) QKV: [8] x (1536 x 1024 x 512)
    k_qkv<<<dim3(8, 12, BB), 256>>>(w_qkv, b_qkv);
    // 3) Fused flash attention: 8 t-tiles x 64 bh
    k_flash<<<dim3(8, 64), 256, FSMEM>>>();
    // 4) proj: [8] x (512 x 1024 x 512)
    k_proj<<<dim3(8, 4, BB), 256>>>(w_proj, b_proj);
    // 5) GroupNorm2 + residual
    gn2_res_kernel<<<BB * GG, 256>>>(x, gn2_s, gn2_b, out);
}